// round 1
// baseline (speedup 1.0000x reference)
#include <cuda_runtime.h>
#include <cuda_bf16.h>
#include <math.h>

// TOF PET forward projection.
// Grid 128^3, box [-200,200]^3, voxel 3.125mm, 128 samples/LOR,
// TOF sigma^2=900 (sigma=30, cutoff 90mm), bin=5.
//
// One warp per LOR. Lane l handles samples k = l, l+32, l+64, l+96.
// The TOF Gaussian cutoff makes a contiguous active k-window; we compute it
// analytically and predicate the expensive body (3 divides + gather + exp)
// outside it. Samples outside the window contribute exactly 0 in the
// reference (jnp.where), so skipping them is exact.

#define N_SAMPLES 128
#define GRID_N    128
// norm = TOF_BIN / sqrt(2*pi*TOF_SIGMA2), computed in double, rounded to f32
#define TOF_NORM  0.06649038006690422f

__global__ __launch_bounds__(256)
void proj_kernel(const float* __restrict__ image,
                 const float* __restrict__ lors,
                 float* __restrict__ out,
                 int n_lors)
{
    const int warp_id = (blockIdx.x * blockDim.x + threadIdx.x) >> 5;
    const int lane    = threadIdx.x & 31;
    if (warp_id >= n_lors) return;

    // ---- per-LOR setup (redundant across lanes; broadcast loads) ----
    const float* l7 = lors + (size_t)warp_id * 7;
    const float p1x = l7[0], p1y = l7[1], p1z = l7[2];
    const float dx  = l7[3] - p1x;
    const float dy  = l7[4] - p1y;
    const float dz  = l7[5] - p1z;
    const float tof = l7[6];

    const float L = sqrtf(dx*dx + dy*dy + dz*dz);

    // safe_d = where(|d| < 1e-8, 1e-8, d)  (matches reference: +eps regardless of sign)
    const float eps = 1e-8f;
    const float sdx = (fabsf(dx) < eps) ? eps : dx;
    const float sdy = (fabsf(dy) < eps) ? eps : dy;
    const float sdz = (fabsf(dz) < eps) ? eps : dz;

    const float bmin = -200.0f, bmax = 200.0f;

    float tax = (bmin - p1x) / sdx, tbx = (bmax - p1x) / sdx;
    float tay = (bmin - p1y) / sdy, tby = (bmax - p1y) / sdy;
    float taz = (bmin - p1z) / sdz, tbz = (bmax - p1z) / sdz;

    float tmin = fmaxf(fmaxf(fminf(tax, tbx), fminf(tay, tby)), fminf(taz, tbz));
    tmin = fmaxf(tmin, 0.0f);
    float tmax = fminf(fminf(fmaxf(tax, tbx), fmaxf(tay, tby)), fmaxf(taz, tbz));
    tmax = fminf(tmax, 1.0f);

    const float valid = (tmax > tmin) ? 1.0f : 0.0f;
    const float span  = fmaxf(tmax - tmin, 0.0f);

    // ---- active k-window from the TOF cutoff ----
    // s(k) = (t(k)-0.5)*L, active iff |s - tof| <= 90.
    // t in [0.5+(tof-90)/L, 0.5+(tof+90)/L]; k(t) = (t-tmin)/span*128 - 0.5.
    // Widened by +-1; NaN/Inf from L->0 or span->0 collapse to full range via
    // fmaxf/fminf, and the per-sample |dev|<=90 predicate keeps it exact.
    const float t_lo = 0.5f + (tof - 90.0f) / L;
    const float t_hi = 0.5f + (tof + 90.0f) / L;
    const float inv_span_scaled = 128.0f / span;
    const int klo = (int)fmaxf(0.0f,   floorf((t_lo - tmin) * inv_span_scaled - 0.5f) - 1.0f);
    const int khi = (int)fminf(127.0f, ceilf ((t_hi - tmin) * inv_span_scaled - 0.5f) + 1.0f);

    float acc = 0.0f;

    #pragma unroll
    for (int j = 0; j < 4; ++j) {
        const int k = lane + 32 * j;
        const float frac = ((float)k + 0.5f) * (1.0f / 128.0f);
        const float t = tmin + frac * span;
        const float s = (t - 0.5f) * L;
        const float dev = s - tof;

        if (k >= klo && k <= khi && fabsf(dev) <= 90.0f) {
            const float px = p1x + t * dx;
            const float py = p1y + t * dy;
            const float pz = p1z + t * dz;
            // IEEE division to match reference floor() boundaries exactly
            int ix = (int)floorf((px - bmin) / 3.125f);
            int iy = (int)floorf((py - bmin) / 3.125f);
            int iz = (int)floorf((pz - bmin) / 3.125f);
            ix = min(GRID_N - 1, max(0, ix));
            iy = min(GRID_N - 1, max(0, iy));
            iz = min(GRID_N - 1, max(0, iz));
            const float val = __ldg(&image[((ix << 7) + iy << 7) + iz]);
            const float w = __expf(dev * dev * (-0.5f / 900.0f));
            acc = fmaf(val, w, acc);
        }
    }

    // ---- warp reduction ----
    #pragma unroll
    for (int off = 16; off > 0; off >>= 1)
        acc += __shfl_xor_sync(0xFFFFFFFFu, acc, off);

    if (lane == 0) {
        const float step = span * L * (1.0f / 128.0f);
        out[warp_id] = acc * TOF_NORM * step * valid;
    }
}

extern "C" void kernel_launch(void* const* d_in, const int* in_sizes, int n_in,
                              void* d_out, int out_size)
{
    const float* image = (const float*)d_in[0];
    const float* lors  = (const float*)d_in[1];
    float* out = (float*)d_out;
    const int n_lors = in_sizes[1] / 7;

    const int threads = 256;               // 8 warps = 8 LORs per block
    const int blocks  = (n_lors * 32 + threads - 1) / threads;
    proj_kernel<<<blocks, threads>>>(image, lors, out, n_lors);
}

// round 2
// speedup vs baseline: 1.3203x; 1.3203x over previous
#include <cuda_runtime.h>
#include <cuda_bf16.h>
#include <math.h>

// TOF PET forward projection. Grid 128^3, box [-200,200]^3, voxel 3.125mm,
// 128 samples/LOR, TOF sigma=30mm, cutoff 90mm, bin=5.
//
// One warp per LOR; loop re-anchored at the analytically computed active
// k-window [klo,khi] (TOF cutoff makes the active set contiguous; samples
// outside contribute exactly 0 in the reference). Lane l handles
// k = klo + 32j + l. Per-LOR slab setup keeps IEEE divides (errors there
// shift every sample); per-sample voxel indexing uses *0.32f (1.5ulp vs
// IEEE /3.125 -> floor flips ~1e-5 of samples, well inside tolerance).

#define GRID_N   128
// TOF_BIN / sqrt(2*pi*TOF_SIGMA2) in double, rounded to f32
#define TOF_NORM 0.06649038006690422f

__global__ __launch_bounds__(256)
void proj_kernel(const float* __restrict__ image,
                 const float* __restrict__ lors,
                 float* __restrict__ out,
                 int n_lors)
{
    const int warp_id = (blockIdx.x * blockDim.x + threadIdx.x) >> 5;
    const int lane    = threadIdx.x & 31;
    if (warp_id >= n_lors) return;

    // ---- per-LOR setup (uniform across lanes; one warp instruction each) ----
    const float* l7 = lors + (size_t)warp_id * 7;
    const float p1x = l7[0], p1y = l7[1], p1z = l7[2];
    const float dx  = l7[3] - p1x;
    const float dy  = l7[4] - p1y;
    const float dz  = l7[5] - p1z;
    const float tof = l7[6];

    const float L = sqrtf(dx*dx + dy*dy + dz*dz);

    // safe_d = where(|d| < 1e-8, 1e-8, d)  (matches reference: +eps)
    const float eps = 1e-8f;
    const float sdx = (fabsf(dx) < eps) ? eps : dx;
    const float sdy = (fabsf(dy) < eps) ? eps : dy;
    const float sdz = (fabsf(dz) < eps) ? eps : dz;

    const float bmin = -200.0f, bmax = 200.0f;

    // IEEE divides here: these shift every sample of the ray.
    float tax = (bmin - p1x) / sdx, tbx = (bmax - p1x) / sdx;
    float tay = (bmin - p1y) / sdy, tby = (bmax - p1y) / sdy;
    float taz = (bmin - p1z) / sdz, tbz = (bmax - p1z) / sdz;

    float tmin = fmaxf(fmaxf(fminf(tax, tbx), fminf(tay, tby)), fminf(taz, tbz));
    tmin = fmaxf(tmin, 0.0f);
    float tmax = fminf(fminf(fmaxf(tax, tbx), fmaxf(tay, tby)), fmaxf(taz, tbz));
    tmax = fminf(tmax, 1.0f);

    const float valid = (tmax > tmin) ? 1.0f : 0.0f;
    const float span  = fmaxf(tmax - tmin, 0.0f);

    // ---- active k-window (fast divides fine: window widened by +-1 and the
    // exact per-sample |dev|<=90 predicate still applies; NaN/Inf collapse
    // to the full range via fmaxf/fminf) ----
    const float rL   = __fdividef(1.0f, L);
    const float t_lo = fmaf(tof - 90.0f, rL, 0.5f);
    const float t_hi = fmaf(tof + 90.0f, rL, 0.5f);
    const float rs   = __fdividef(128.0f, span);
    const float klo_f = floorf(fmaf(t_lo - tmin, rs, -0.5f)) - 1.0f;
    const float khi_f = ceilf (fmaf(t_hi - tmin, rs, -0.5f)) + 1.0f;
    const int klo = (int)fmaxf(klo_f, 0.0f);     // fmaxf(NaN,0)=0
    const int khi = (int)fminf(khi_f, 127.0f);   // fminf(NaN,127)=127

    float acc = 0.0f;

    for (int k0 = klo; k0 <= khi; k0 += 32) {
        const int k = k0 + lane;
        const float fk = (float)k;
        // frac = (k+0.5)/128 exactly (power-of-two denominator)
        const float frac = fmaf(fk, 0.0078125f, 0.00390625f);
        const float t = fmaf(frac, span, tmin);
        const float s = (t - 0.5f) * L;
        const float dev = s - tof;

        if (k <= khi && fabsf(dev) <= 90.0f) {
            const float bx = fmaf(t, dx, p1x) + 200.0f;
            const float by = fmaf(t, dy, p1y) + 200.0f;
            const float bz = fmaf(t, dz, p1z) + 200.0f;
            int ix = __float2int_rd(bx * 0.32f);
            int iy = __float2int_rd(by * 0.32f);
            int iz = __float2int_rd(bz * 0.32f);
            ix = min(GRID_N - 1, max(0, ix));
            iy = min(GRID_N - 1, max(0, iy));
            iz = min(GRID_N - 1, max(0, iz));
            const float val = __ldg(&image[(((ix << 7) + iy) << 7) + iz]);
            const float w = __expf(dev * dev * (-0.5f / 900.0f));
            acc = fmaf(val, w, acc);
        }
    }

    // ---- warp reduction ----
    #pragma unroll
    for (int off = 16; off > 0; off >>= 1)
        acc += __shfl_xor_sync(0xFFFFFFFFu, acc, off);

    if (lane == 0) {
        const float step = span * L * (1.0f / 128.0f);
        out[warp_id] = acc * TOF_NORM * step * valid;
    }
}

extern "C" void kernel_launch(void* const* d_in, const int* in_sizes, int n_in,
                              void* d_out, int out_size)
{
    const float* image = (const float*)d_in[0];
    const float* lors  = (const float*)d_in[1];
    float* out = (float*)d_out;
    const int n_lors = in_sizes[1] / 7;

    const int threads = 256;   // 8 warps = 8 LORs per block
    const int blocks  = (n_lors * 32 + threads - 1) / threads;
    proj_kernel<<<blocks, threads>>>(image, lors, out, n_lors);
}

// round 3
// speedup vs baseline: 1.5527x; 1.1760x over previous
#include <cuda_runtime.h>
#include <cuda_bf16.h>
#include <math.h>

// TOF PET forward projection. Grid 128^3, box [-200,200]^3, voxel 3.125mm,
// 128 samples/LOR, TOF sigma=30mm, cutoff 90mm, bin=5.
//
// One warp per LOR. All per-sample quantities (dev, voxel coords) are affine
// in the sample index k; slopes/offsets are precomputed per LOR so the inner
// loop is a handful of FFMA + F2I + clamp + LDG + EX2. The TOF cutoff gives a
// contiguous active k-window, computed analytically in dev-space (dL >= 0)
// and widened by +-1; the exact |dev|<=90 predicate is still applied, so
// skipping outside samples is exact (reference zeroes them).

#define GRID_N   128
// TOF_BIN / sqrt(2*pi*TOF_SIGMA2), double-computed, rounded to f32
#define TOF_NORM 0.06649038006690422f
// -log2(e) / (2*900): exp(-dev^2/1800) == exp2(dev^2 * C2)
#define C2_EXP  (-8.0158841e-4f)

__global__ __launch_bounds__(256)
void proj_kernel(const float* __restrict__ image,
                 const float* __restrict__ lors,
                 float* __restrict__ out,
                 int n_lors)
{
    const int warp_id = (blockIdx.x * blockDim.x + threadIdx.x) >> 5;
    const int lane    = threadIdx.x & 31;
    if (warp_id >= n_lors) return;

    // ---- per-LOR setup (uniform across lanes) ----
    const float* l7 = lors + (size_t)warp_id * 7;
    const float p1x = l7[0], p1y = l7[1], p1z = l7[2];
    const float dx  = l7[3] - p1x;
    const float dy  = l7[4] - p1y;
    const float dz  = l7[5] - p1z;
    const float tof = l7[6];

    const float L = sqrtf(fmaf(dx, dx, fmaf(dy, dy, dz * dz)));

    // safe_d = where(|d| < 1e-8, 1e-8, d)  (matches reference: +eps)
    const float eps = 1e-8f;
    const float sdx = (fabsf(dx) < eps) ? eps : dx;
    const float sdy = (fabsf(dy) < eps) ? eps : dy;
    const float sdz = (fabsf(dz) < eps) ? eps : dz;

    // slab intersection via fast reciprocals (error ~2ulp; shifts sample
    // positions by ~1e-7 relative, far inside tolerance)
    const float rx = __fdividef(1.0f, sdx);
    const float ry = __fdividef(1.0f, sdy);
    const float rz = __fdividef(1.0f, sdz);
    const float tax = (-200.0f - p1x) * rx, tbx = (200.0f - p1x) * rx;
    const float tay = (-200.0f - p1y) * ry, tby = (200.0f - p1y) * ry;
    const float taz = (-200.0f - p1z) * rz, tbz = (200.0f - p1z) * rz;

    float tmin = fmaxf(fmaxf(fminf(tax, tbx), fminf(tay, tby)), fminf(taz, tbz));
    tmin = fmaxf(tmin, 0.0f);
    float tmax = fminf(fminf(fmaxf(tax, tbx), fmaxf(tay, tby)), fmaxf(taz, tbz));
    tmax = fminf(tmax, 1.0f);

    const float valid = (tmax > tmin) ? 1.0f : 0.0f;
    const float span  = fmaxf(tmax - tmin, 0.0f);

    // ---- affine-in-k coefficients ----
    const float cs = span * 0.0078125f;          // dt per sample
    const float t0 = fmaf(0.5f, cs, tmin);       // t at k=0
    const float dL   = cs * L;                   // d(dev)/dk  (>= 0)
    const float dev0 = fmaf(t0 - 0.5f, L, -tof); // dev at k=0
    // voxel-space coords: g?(k) = fmaf(fk, gs?, g?0)
    const float gsx = cs * dx * 0.32f;
    const float gsy = cs * dy * 0.32f;
    const float gsz = cs * dz * 0.32f;
    const float gx0 = (fmaf(t0, dx, p1x) + 200.0f) * 0.32f;
    const float gy0 = (fmaf(t0, dy, p1y) + 200.0f) * 0.32f;
    const float gz0 = (fmaf(t0, dz, p1z) + 200.0f) * 0.32f;

    // ---- active k-window: |dev0 + fk*dL| <= 90, dL >= 0.
    // Widened by +-1; dL==0 -> rdL=inf: both bounds +-inf/NaN, handled by
    // the clamps + F2I saturation, and the per-sample predicate stays exact.
    const float rdL = __fdividef(1.0f, dL);
    const float klo_f = floorf((-90.0f - dev0) * rdL) - 1.0f;
    const float khi_f = ceilf (( 90.0f - dev0) * rdL) + 1.0f;
    const int klo = (int)fmaxf(klo_f, 0.0f);    // fmaxf(NaN,0)=0
    const int khi = (int)fminf(khi_f, 127.0f);  // fminf(NaN,127)=127

    float acc = 0.0f;

    for (int k0 = klo; k0 <= khi; k0 += 32) {
        const int k = k0 + lane;
        const float fk = (float)k;
        const float dev = fmaf(fk, dL, dev0);

        if (k <= khi && fabsf(dev) <= 90.0f) {
            int ix = __float2int_rd(fmaf(fk, gsx, gx0));
            int iy = __float2int_rd(fmaf(fk, gsy, gy0));
            int iz = __float2int_rd(fmaf(fk, gsz, gz0));
            ix = min(GRID_N - 1, max(0, ix));
            iy = min(GRID_N - 1, max(0, iy));
            iz = min(GRID_N - 1, max(0, iz));
            const float val = __ldg(&image[(((ix << 7) + iy) << 7) + iz]);
            const float w = exp2f(dev * dev * C2_EXP);
            acc = fmaf(val, w, acc);
        }
    }

    // ---- warp reduction ----
    #pragma unroll
    for (int off = 16; off > 0; off >>= 1)
        acc += __shfl_xor_sync(0xFFFFFFFFu, acc, off);

    if (lane == 0) {
        const float step = span * L * (1.0f / 128.0f);
        out[warp_id] = acc * TOF_NORM * step * valid;
    }
}

extern "C" void kernel_launch(void* const* d_in, const int* in_sizes, int n_in,
                              void* d_out, int out_size)
{
    const float* image = (const float*)d_in[0];
    const float* lors  = (const float*)d_in[1];
    float* out = (float*)d_out;
    const int n_lors = in_sizes[1] / 7;

    const int threads = 256;   // 8 warps = 8 LORs per block
    const int blocks  = (n_lors * 32 + threads - 1) / threads;
    proj_kernel<<<blocks, threads>>>(image, lors, out, n_lors);
}

// round 4
// speedup vs baseline: 1.9397x; 1.2493x over previous
#include <cuda_runtime.h>
#include <cuda_bf16.h>
#include <math.h>

// TOF PET forward projection. Grid 128^3, box [-200,200]^3, voxel 3.125mm,
// 128 samples/LOR, TOF sigma=30mm, cutoff 90mm, bin=5.
//
// TWO LORs per warp: lanes 0-15 handle LOR 2w, lanes 16-31 handle LOR 2w+1.
// The (uniform-per-LOR) setup is thereby SIMD across LORs, halving its issue
// cost. All per-sample quantities are affine in sample index k; the TOF
// cutoff gives a contiguous active k-window computed analytically (widened
// +-1, exact |dev|<=90 predicate retained, so skipping is exact).
// Voxel clamps use fabs (lower, rounding-only negatives) + fminf 127.99
// (upper) to move work off the saturated ALU pipe.

#define GRID_N   128
// TOF_BIN / sqrt(2*pi*TOF_SIGMA2), double-computed, rounded to f32
#define TOF_NORM 0.06649038006690422f
// -log2(e) / (2*900): exp(-dev^2/1800) == exp2(dev^2 * C2)
#define C2_EXP  (-8.0158841e-4f)

__global__ __launch_bounds__(256)
void proj_kernel(const float* __restrict__ image,
                 const float* __restrict__ lors,
                 float* __restrict__ out,
                 int n_lors)
{
    const int warp_id = (blockIdx.x * blockDim.x + threadIdx.x) >> 5;
    const int lane    = threadIdx.x & 31;
    const int sub     = lane & 15;           // lane within half-warp
    int lor = warp_id * 2 + (lane >> 4);
    const bool live = (lor < n_lors);
    if (warp_id * 2 >= n_lors) return;
    if (!live) lor = 0;                       // harmless dummy work, no store

    // ---- per-LOR setup (uniform across each half-warp) ----
    const float* l7 = lors + (size_t)lor * 7;
    const float p1x = l7[0], p1y = l7[1], p1z = l7[2];
    const float dx  = l7[3] - p1x;
    const float dy  = l7[4] - p1y;
    const float dz  = l7[5] - p1z;
    const float tof = l7[6];

    const float L = sqrtf(fmaf(dx, dx, fmaf(dy, dy, dz * dz)));

    // safe_d = where(|d| < 1e-8, 1e-8, d)  (matches reference: +eps)
    const float eps = 1e-8f;
    const float sdx = (fabsf(dx) < eps) ? eps : dx;
    const float sdy = (fabsf(dy) < eps) ? eps : dy;
    const float sdz = (fabsf(dz) < eps) ? eps : dz;

    // slab intersection via fast reciprocals (~2ulp; shifts sample positions
    // by ~1e-7 relative, far inside tolerance)
    const float rx = __fdividef(1.0f, sdx);
    const float ry = __fdividef(1.0f, sdy);
    const float rz = __fdividef(1.0f, sdz);
    const float tax = (-200.0f - p1x) * rx, tbx = (200.0f - p1x) * rx;
    const float tay = (-200.0f - p1y) * ry, tby = (200.0f - p1y) * ry;
    const float taz = (-200.0f - p1z) * rz, tbz = (200.0f - p1z) * rz;

    float tmin = fmaxf(fmaxf(fminf(tax, tbx), fminf(tay, tby)), fminf(taz, tbz));
    tmin = fmaxf(tmin, 0.0f);
    float tmax = fminf(fminf(fmaxf(tax, tbx), fmaxf(tay, tby)), fmaxf(taz, tbz));
    tmax = fminf(tmax, 1.0f);

    const float valid = (tmax > tmin) ? 1.0f : 0.0f;
    const float span  = fmaxf(tmax - tmin, 0.0f);

    // ---- affine-in-k coefficients ----
    const float cs = span * 0.0078125f;          // dt per sample
    const float t0 = fmaf(0.5f, cs, tmin);       // t at k=0
    const float dL   = cs * L;                   // d(dev)/dk  (>= 0)
    const float dev0 = fmaf(t0 - 0.5f, L, -tof); // dev at k=0
    // voxel-space coords: g?(k) = fmaf(fk, gs?, g?0)
    const float gsx = cs * dx * 0.32f;
    const float gsy = cs * dy * 0.32f;
    const float gsz = cs * dz * 0.32f;
    const float gx0 = (fmaf(t0, dx, p1x) + 200.0f) * 0.32f;
    const float gy0 = (fmaf(t0, dy, p1y) + 200.0f) * 0.32f;
    const float gz0 = (fmaf(t0, dz, p1z) + 200.0f) * 0.32f;

    // ---- active k-window: |dev0 + fk*dL| <= 90, dL >= 0.
    // Widened +-1; dL==0 -> rdL=inf -> NaN bounds collapse to [0,127] via
    // fmaxf/fminf; per-sample predicates keep everything exact.
    const float rdL = __fdividef(1.0f, dL);
    const float klo_f = floorf((-90.0f - dev0) * rdL) - 1.0f;
    const float khi_f = ceilf (( 90.0f - dev0) * rdL) + 1.0f;
    const int klo = (int)fmaxf(klo_f, 0.0f);    // fmaxf(NaN,0)=0
    const int khi = (int)fminf(khi_f, 127.0f);  // fminf(NaN,127)=127

    float acc = 0.0f;

    for (int k0 = klo; k0 <= khi; k0 += 16) {
        const int k = k0 + sub;
        const float fk = (float)k;
        const float dev = fmaf(fk, dL, dev0);

        if (k <= khi && fabsf(dev) <= 90.0f) {
            // lower clamp via fabs (true values never <= -1; only rounding
            // -eps occurs, fabs maps it to +eps -> floor 0 == clamp),
            // upper clamp via fminf(.,127.99) (128.0 -> 127 == clamp)
            const int ix = __float2int_rd(fminf(fabsf(fmaf(fk, gsx, gx0)), 127.99f));
            const int iy = __float2int_rd(fminf(fabsf(fmaf(fk, gsy, gy0)), 127.99f));
            const int iz = __float2int_rd(fminf(fabsf(fmaf(fk, gsz, gz0)), 127.99f));
            const float val = __ldg(&image[ix * 16384 + iy * 128 + iz]);
            const float w = exp2f(dev * dev * C2_EXP);
            acc = fmaf(val, w, acc);
        }
    }

    // ---- half-warp reduction (xor offsets stay within each 16-lane half) ----
    #pragma unroll
    for (int off = 8; off > 0; off >>= 1)
        acc += __shfl_xor_sync(0xFFFFFFFFu, acc, off);

    if (sub == 0 && live) {
        const float step = span * L * (1.0f / 128.0f);
        out[lor] = acc * TOF_NORM * step * valid;
    }
}

extern "C" void kernel_launch(void* const* d_in, const int* in_sizes, int n_in,
                              void* d_out, int out_size)
{
    const float* image = (const float*)d_in[0];
    const float* lors  = (const float*)d_in[1];
    float* out = (float*)d_out;
    const int n_lors = in_sizes[1] / 7;

    const int threads = 256;                       // 8 warps = 16 LORs/block
    const int n_warps = (n_lors + 1) / 2;
    const int blocks  = (n_warps * 32 + threads - 1) / threads;
    proj_kernel<<<blocks, threads>>>(image, lors, out, n_lors);
}

// round 5
// speedup vs baseline: 2.2586x; 1.1644x over previous
#include <cuda_runtime.h>
#include <cuda_bf16.h>
#include <math.h>

// TOF PET forward projection. Grid 128^3, box [-200,200]^3, voxel 3.125mm,
// 128 samples/LOR, TOF sigma=30mm, cutoff 90mm, bin=5.
//
// FOUR LORs per warp: 8-lane subgroups, so the uniform per-LOR setup is SIMD
// across 4 LORs. All per-sample quantities are affine in the sample index k;
// the Gaussian is evaluated in u-space (u = dev*sqrt(log2e/1800)) so the
// weight is exp2(-u*u) (one FMUL with neg modifier + EX2). The TOF cutoff
// gives a contiguous active k-window, computed analytically (widened +-1)
// with the per-sample cutoff predicate retained, so skipping is exact.

#define GRID_N   128
// TOF_BIN / sqrt(2*pi*TOF_SIGMA2), double-computed, rounded to f32
#define TOF_NORM 0.06649038006690422f
// sC = sqrt(log2(e)/1800); dev^2*log2e/1800 == (dev*sC)^2
#define SC_U     0.028310727f
// 90 * SC_U
#define UTHR     2.5479655f

__global__ __launch_bounds__(256)
void proj_kernel(const float* __restrict__ image,
                 const float* __restrict__ lors,
                 float* __restrict__ out,
                 int n_lors)
{
    const int warp_id = (blockIdx.x * blockDim.x + threadIdx.x) >> 5;
    const int lane    = threadIdx.x & 31;
    const int sub     = lane & 7;            // lane within 8-lane subgroup
    if (warp_id * 4 >= n_lors) return;
    int lor = warp_id * 4 + (lane >> 3);
    const bool live = (lor < n_lors);
    if (!live) lor = 0;                      // dummy work, no store

    // ---- per-LOR setup (uniform across each 8-lane subgroup) ----
    const float* l7 = lors + (size_t)lor * 7;
    const float p1x = l7[0], p1y = l7[1], p1z = l7[2];
    const float dx  = l7[3] - p1x;
    const float dy  = l7[4] - p1y;
    const float dz  = l7[5] - p1z;
    const float tof = l7[6];

    const float L = sqrtf(fmaf(dx, dx, fmaf(dy, dy, dz * dz)));

    // safe_d = where(|d| < 1e-8, 1e-8, d)  (matches reference: +eps)
    const float eps = 1e-8f;
    const float sdx = (fabsf(dx) < eps) ? eps : dx;
    const float sdy = (fabsf(dy) < eps) ? eps : dy;
    const float sdz = (fabsf(dz) < eps) ? eps : dz;

    // slab intersection via fast reciprocals (~2ulp)
    const float rx = __fdividef(1.0f, sdx);
    const float ry = __fdividef(1.0f, sdy);
    const float rz = __fdividef(1.0f, sdz);
    const float tax = (-200.0f - p1x) * rx, tbx = (200.0f - p1x) * rx;
    const float tay = (-200.0f - p1y) * ry, tby = (200.0f - p1y) * ry;
    const float taz = (-200.0f - p1z) * rz, tbz = (200.0f - p1z) * rz;

    float tmin = fmaxf(fmaxf(fminf(tax, tbx), fminf(tay, tby)), fminf(taz, tbz));
    tmin = fmaxf(tmin, 0.0f);
    float tmax = fminf(fminf(fmaxf(tax, tbx), fmaxf(tay, tby)), fmaxf(taz, tbz));
    tmax = fminf(tmax, 1.0f);

    const float valid = (tmax > tmin) ? 1.0f : 0.0f;
    const float span  = fmaxf(tmax - tmin, 0.0f);

    // ---- affine-in-k coefficients ----
    const float cs = span * 0.0078125f;          // dt per sample
    const float t0 = fmaf(0.5f, cs, tmin);       // t at k=0
    const float dL   = cs * L;                   // d(dev)/dk (>= 0)
    const float dev0 = fmaf(t0 - 0.5f, L, -tof); // dev at k=0
    const float du   = dL   * SC_U;              // u slope
    const float u0   = dev0 * SC_U;              // u at k=0
    const float gsx = cs * dx * 0.32f;
    const float gsy = cs * dy * 0.32f;
    const float gsz = cs * dz * 0.32f;
    const float gx0 = (fmaf(t0, dx, p1x) + 200.0f) * 0.32f;
    const float gy0 = (fmaf(t0, dy, p1y) + 200.0f) * 0.32f;
    const float gz0 = (fmaf(t0, dz, p1z) + 200.0f) * 0.32f;

    // ---- active k-window: |dev0 + fk*dL| <= 90, dL >= 0. Widened +-1.
    // Degenerate dL=0 -> rdL=inf: signs/NaN collapse to the correct window
    // through fmaxf/fminf and F2I saturation (verified case-by-case).
    const float rdL = __fdividef(1.0f, dL);
    const float klo_f = floorf((-90.0f - dev0) * rdL) - 1.0f;
    const float khi_f = ceilf (( 90.0f - dev0) * rdL) + 1.0f;
    const int klo = (int)fmaxf(klo_f, 0.0f);    // fmaxf(NaN,0)=0
    const int khi = (int)fminf(khi_f, 127.0f);  // fminf(NaN,127)=127

    float acc = 0.0f;
    int niter = ((khi - klo) >> 3) + 1;          // <=0 when window empty
    float fk = (float)(klo + sub);               // exact small ints
    const float fkhi = (float)khi;

    for (; niter > 0; --niter) {
        const float u = fmaf(fk, du, u0);
        if (fk <= fkhi && fabsf(u) <= UTHR) {
            // lower clamp via fabs (true coords never <= -1, only rounding
            // -eps, which fabs maps to +eps -> floor 0 == clamp); upper via
            // fminf(.,127.99) (128.0 -> 127 == clamp)
            const int ix = __float2int_rd(fminf(fabsf(fmaf(fk, gsx, gx0)), 127.99f));
            const int iy = __float2int_rd(fminf(fabsf(fmaf(fk, gsy, gy0)), 127.99f));
            const int iz = __float2int_rd(fminf(fabsf(fmaf(fk, gsz, gz0)), 127.99f));
            const float val = __ldg(&image[ix * 16384 + iy * 128 + iz]);
            const float w = exp2f(-u * u);
            acc = fmaf(val, w, acc);
        }
        fk += 8.0f;
    }

    // ---- 8-lane subgroup reduction ----
    #pragma unroll
    for (int off = 4; off > 0; off >>= 1)
        acc += __shfl_xor_sync(0xFFFFFFFFu, acc, off);

    if (sub == 0 && live) {
        const float step = span * L * (1.0f / 128.0f);
        out[lor] = acc * TOF_NORM * step * valid;
    }
}

extern "C" void kernel_launch(void* const* d_in, const int* in_sizes, int n_in,
                              void* d_out, int out_size)
{
    const float* image = (const float*)d_in[0];
    const float* lors  = (const float*)d_in[1];
    float* out = (float*)d_out;
    const int n_lors = in_sizes[1] / 7;

    const int threads = 256;                       // 8 warps = 32 LORs/block
    const int n_warps = (n_lors + 3) / 4;
    const int blocks  = (n_warps * 32 + threads - 1) / threads;
    proj_kernel<<<blocks, threads>>>(image, lors, out, n_lors);
}

// round 7
// speedup vs baseline: 2.3766x; 1.0523x over previous
#include <cuda_runtime.h>
#include <cuda_bf16.h>
#include <math.h>

// TOF PET forward projection. Grid 128^3, box [-200,200]^3, voxel 3.125mm,
// 128 samples/LOR, TOF sigma=30mm, cutoff 90mm, bin=5.
//
// FOUR LORs per warp (8-lane subgroups): uniform per-LOR setup is SIMD
// across 4 LORs. Per-sample quantities are affine in sample index k; the
// Gaussian is evaluated in u-space (u = dev*sqrt(log2e/1800)) so the weight
// is exp2(-u*u). The TOF cutoff gives a contiguous active k-window computed
// analytically (widened +-1). Per-sample predicate: |u|<=UTHR (exact TOF
// cutoff) AND fk<=127 (sample-range tail guard — REQUIRED: when the window
// clamps at khi=127, overshoot lanes k=128..134 are still inside the TOF
// cutoff and must not contribute; this is what broke R5).

#define GRID_N   128
// TOF_BIN / sqrt(2*pi*TOF_SIGMA2), double-computed, rounded to f32
#define TOF_NORM 0.06649038006690422f
// sC = sqrt(log2(e)/1800); dev^2*log2e/1800 == (dev*sC)^2
#define SC_U     0.028310727f
// 90 * SC_U
#define UTHR     2.5479655f

__global__ __launch_bounds__(256)
void proj_kernel(const float* __restrict__ image,
                 const float* __restrict__ lors,
                 float* __restrict__ out,
                 int n_lors)
{
    const int warp_id = (blockIdx.x * blockDim.x + threadIdx.x) >> 5;
    const int lane    = threadIdx.x & 31;
    const int sub     = lane & 7;            // lane within 8-lane subgroup
    if (warp_id * 4 >= n_lors) return;
    int lor = warp_id * 4 + (lane >> 3);
    const bool live = (lor < n_lors);
    if (!live) lor = 0;                      // dummy work, no store

    // ---- per-LOR setup (uniform across each 8-lane subgroup) ----
    const float* l7 = lors + (size_t)lor * 7;
    const float p1x = l7[0], p1y = l7[1], p1z = l7[2];
    const float dx  = l7[3] - p1x;
    const float dy  = l7[4] - p1y;
    const float dz  = l7[5] - p1z;
    const float tof = l7[6];

    const float L = sqrtf(fmaf(dx, dx, fmaf(dy, dy, dz * dz)));

    // safe_d = where(|d| < 1e-8, 1e-8, d)  (matches reference: +eps)
    const float eps = 1e-8f;
    const float sdx = (fabsf(dx) < eps) ? eps : dx;
    const float sdy = (fabsf(dy) < eps) ? eps : dy;
    const float sdz = (fabsf(dz) < eps) ? eps : dz;

    // slab intersection via fast reciprocals (~2ulp)
    const float rx = __fdividef(1.0f, sdx);
    const float ry = __fdividef(1.0f, sdy);
    const float rz = __fdividef(1.0f, sdz);
    const float tax = (-200.0f - p1x) * rx, tbx = (200.0f - p1x) * rx;
    const float tay = (-200.0f - p1y) * ry, tby = (200.0f - p1y) * ry;
    const float taz = (-200.0f - p1z) * rz, tbz = (200.0f - p1z) * rz;

    float tmin = fmaxf(fmaxf(fminf(tax, tbx), fminf(tay, tby)), fminf(taz, tbz));
    tmin = fmaxf(tmin, 0.0f);
    float tmax = fminf(fminf(fmaxf(tax, tbx), fmaxf(tay, tby)), fmaxf(taz, tbz));
    tmax = fminf(tmax, 1.0f);

    const float valid = (tmax > tmin) ? 1.0f : 0.0f;
    const float span  = fmaxf(tmax - tmin, 0.0f);

    // ---- affine-in-k coefficients ----
    const float cs = span * 0.0078125f;          // dt per sample
    const float t0 = fmaf(0.5f, cs, tmin);       // t at k=0
    const float dL   = cs * L;                   // d(dev)/dk (>= 0)
    const float dev0 = fmaf(t0 - 0.5f, L, -tof); // dev at k=0
    const float du   = dL   * SC_U;              // u slope
    const float u0   = dev0 * SC_U;              // u at k=0
    const float gsx = cs * dx * 0.32f;
    const float gsy = cs * dy * 0.32f;
    const float gsz = cs * dz * 0.32f;
    const float gx0 = (fmaf(t0, dx, p1x) + 200.0f) * 0.32f;
    const float gy0 = (fmaf(t0, dy, p1y) + 200.0f) * 0.32f;
    const float gz0 = (fmaf(t0, dz, p1z) + 200.0f) * 0.32f;

    // ---- active k-window: |dev0 + fk*dL| <= 90, dL >= 0. Widened +-1.
    // Degenerate dL=0 -> rdL=inf: NaN/inf bounds collapse correctly via
    // fmaxf/fminf and F2I saturation.
    const float rdL = __fdividef(1.0f, dL);
    const float klo_f = floorf((-90.0f - dev0) * rdL) - 1.0f;
    const float khi_f = ceilf (( 90.0f - dev0) * rdL) + 1.0f;
    const int klo = (int)fmaxf(klo_f, 0.0f);    // fmaxf(NaN,0)=0
    const int khi = (int)fminf(khi_f, 127.0f);  // fminf(NaN,127)=127

    int niter = ((khi - klo) >> 3) + 1;          // <=0 when window empty
    if (!(tmax > tmin)) niter = 0;               // skip box-missing rays
    float fk = (float)(klo + sub);               // exact small ints
    float acc = 0.0f;

    #pragma unroll 2
    for (; niter > 0; --niter) {
        const float u = fmaf(fk, du, u0);
        if (fabsf(u) <= UTHR && fk <= 127.0f) {
            // lower clamp via fabs (true coords never <= -1, only rounding
            // -eps -> +eps -> floor 0 == clamp); upper via fminf(.,127.99)
            const int ix = __float2int_rd(fminf(fabsf(fmaf(fk, gsx, gx0)), 127.99f));
            const int iy = __float2int_rd(fminf(fabsf(fmaf(fk, gsy, gy0)), 127.99f));
            const int iz = __float2int_rd(fminf(fabsf(fmaf(fk, gsz, gz0)), 127.99f));
            const float val = __ldg(&image[ix * 16384 + iy * 128 + iz]);
            const float w = exp2f(-u * u);
            acc = fmaf(val, w, acc);
        }
        fk += 8.0f;
    }

    // ---- 8-lane subgroup reduction ----
    #pragma unroll
    for (int off = 4; off > 0; off >>= 1)
        acc += __shfl_xor_sync(0xFFFFFFFFu, acc, off);

    if (sub == 0 && live) {
        const float step = span * L * (1.0f / 128.0f);
        out[lor] = acc * TOF_NORM * step * valid;
    }
}

extern "C" void kernel_launch(void* const* d_in, const int* in_sizes, int n_in,
                              void* d_out, int out_size)
{
    const float* image = (const float*)d_in[0];
    const float* lors  = (const float*)d_in[1];
    float* out = (float*)d_out;
    const int n_lors = in_sizes[1] / 7;

    const int threads = 256;                       // 8 warps = 32 LORs/block
    const int n_warps = (n_lors + 3) / 4;
    const int blocks  = (n_warps * 32 + threads - 1) / threads;
    proj_kernel<<<blocks, threads>>>(image, lors, out, n_lors);
}